// round 6
// baseline (speedup 1.0000x reference)
#include <cuda_runtime.h>
#include <cuda_bf16.h>
#include <cstdint>

#define N_NODES 16384
#define N_EDGES 262144
#define N_GRAPHS 16
#define IN_CH 128
#define HID_CH 256
#define LAT 64
#define MAXDEG 96

#define Z_OFF   0
#define ZG_OFF  (N_NODES*LAT)
#define XH_OFF  (ZG_OFF + N_GRAPHS*LAT)
#define AH_OFF  (XH_OFF + N_NODES*IN_CH)

// ---------------- device scratch ----------------
__device__ float g_aggx[N_NODES*IN_CH];
__device__ float g_h2[N_NODES*HID_CH];
__device__ int   g_cnt_i[N_NODES];
__device__ int   g_csr[N_NODES*MAXDEG];
__device__ float g_zgsum[N_GRAPHS*LAT];
__device__ float g_cnt[N_GRAPHS];
__device__ float g_gout[N_GRAPHS*IN_CH];

// ---------------- helpers ----------------
__device__ __forceinline__ unsigned cvt_tf32(float x) {
    unsigned u;
    asm("cvt.rna.tf32.f32 %0, %1;" : "=r"(u) : "f"(x));
    return u;
}
__device__ __forceinline__ float sigf(float x) {
    float t;
    asm("tanh.approx.f32 %0, %1;" : "=f"(t) : "f"(x * 0.5f));
    return fmaf(0.5f, t, 0.5f);
}
__device__ __forceinline__ void mma_tf32(float* c, const unsigned* a, const unsigned* b) {
    asm volatile(
        "mma.sync.aligned.m16n8k8.row.col.f32.tf32.tf32.f32 "
        "{%0,%1,%2,%3},{%4,%5,%6,%7},{%8,%9},{%0,%1,%2,%3};\n"
        : "+f"(c[0]), "+f"(c[1]), "+f"(c[2]), "+f"(c[3])
        : "r"(a[0]), "r"(a[1]), "r"(a[2]), "r"(a[3]), "r"(b[0]), "r"(b[1]));
}

// ---------------- prep ----------------
__global__ void k_zero() {
    int i = blockIdx.x * blockDim.x + threadIdx.x;
    if (i < N_NODES) g_cnt_i[i] = 0;
    if (i < N_GRAPHS * LAT) g_zgsum[i] = 0.0f;
    if (i < N_GRAPHS) g_cnt[i] = 0.0f;
}

__global__ void k_build(const int* __restrict__ ei) {
    int e = blockIdx.x * blockDim.x + threadIdx.x;
    if (e < N_EDGES) {
        int row = ei[e];
        int col = ei[N_EDGES + e];
        int pos = atomicAdd(&g_cnt_i[col], 1);
        if (pos < MAXDEG) g_csr[col * MAXDEG + pos] = row;
    }
}

// agg_x[n] = dinv_n^2 * x[n] + sum_e dinv_n*dinv_src * x[src]
// 1 warp per node, float4 per lane (one 128B line per gather load).
__global__ __launch_bounds__(128) void k_gatherx(const float* __restrict__ x) {
    __shared__ float w_s[4][MAXDEG];
    __shared__ int   s_s[4][MAXDEG];
    int tid = threadIdx.x;
    int warp = tid >> 5, lane = tid & 31;
    int n = blockIdx.x * 4 + warp;
    int dg = min(g_cnt_i[n], MAXDEG);
    float di = rsqrtf((float)(dg + 1));
    for (int e = lane; e < dg; e += 32) {
        int src = g_csr[n * MAXDEG + e];
        s_s[warp][e] = src;
        w_s[warp][e] = di * rsqrtf((float)(g_cnt_i[src] + 1));
    }
    __syncwarp();
    const float4* x4 = (const float4*)x;
    float4 v = x4[n * 32 + lane];
    float s = di * di;
    float4 acc = make_float4(s * v.x, s * v.y, s * v.z, s * v.w);
#pragma unroll 4
    for (int e = 0; e < dg; e++) {
        float w = w_s[warp][e];
        float4 u = x4[s_s[warp][e] * 32 + lane];
        acc.x = fmaf(w, u.x, acc.x); acc.y = fmaf(w, u.y, acc.y);
        acc.z = fmaf(w, u.z, acc.z); acc.w = fmaf(w, u.w, acc.w);
    }
    ((float4*)g_aggx)[n * 32 + lane] = acc;
}

// ---------------- split-tf32 MMA GEMM ----------------
// C[m][n] = sum_k A[m][k]*B[n][k] (+bias, opt relu). 8 warps 2x4.
// MTILE in {128, 64}: warp covers MTILE/2 rows, MT=MTILE/32 m-frags.
template<int MTILE, int NTILE, int KDIM, int MODE>   // MODE 0: bias+relu, 1: bias
__global__ __launch_bounds__(256) void gemm_mma(
    const float* __restrict__ A, const float* __restrict__ B,
    const float* __restrict__ bias, float* __restrict__ C, int ldc)
{
    constexpr int NT = NTILE / 32;
    constexpr int MT = MTILE / 32;
    __shared__ unsigned Ahi[MTILE][20], Alo[MTILE][20];
    __shared__ unsigned Bhi[NTILE][20], Blo[NTILE][20];
    int tid = threadIdx.x;
    int warp = tid >> 5, lane = tid & 31;
    int wm = warp >> 2, wn = warp & 3;
    int r = lane >> 2, t4 = lane & 3;
    int m0 = blockIdx.y * MTILE, n0 = blockIdx.x * NTILE;

    float acc[MT][NT][4];
#pragma unroll
    for (int mt = 0; mt < MT; mt++)
#pragma unroll
        for (int nt = 0; nt < NT; nt++)
#pragma unroll
            for (int q = 0; q < 4; q++) acc[mt][nt][q] = 0.0f;

    for (int kc = 0; kc < KDIM; kc += 16) {
        __syncthreads();
        for (int i = tid; i < MTILE * 4; i += 256) {
            int rr = i >> 2, q = (i & 3) * 4;
            float4 v = *(const float4*)&A[(size_t)(m0 + rr) * KDIM + kc + q];
            unsigned h0 = cvt_tf32(v.x), h1 = cvt_tf32(v.y),
                     h2 = cvt_tf32(v.z), h3 = cvt_tf32(v.w);
            Ahi[rr][q+0] = h0; Ahi[rr][q+1] = h1; Ahi[rr][q+2] = h2; Ahi[rr][q+3] = h3;
            Alo[rr][q+0] = cvt_tf32(v.x - __uint_as_float(h0));
            Alo[rr][q+1] = cvt_tf32(v.y - __uint_as_float(h1));
            Alo[rr][q+2] = cvt_tf32(v.z - __uint_as_float(h2));
            Alo[rr][q+3] = cvt_tf32(v.w - __uint_as_float(h3));
        }
        for (int i = tid; i < NTILE * 4; i += 256) {
            int rr = i >> 2, q = (i & 3) * 4;
            float4 v = *(const float4*)&B[(size_t)(n0 + rr) * KDIM + kc + q];
            unsigned h0 = cvt_tf32(v.x), h1 = cvt_tf32(v.y),
                     h2 = cvt_tf32(v.z), h3 = cvt_tf32(v.w);
            Bhi[rr][q+0] = h0; Bhi[rr][q+1] = h1; Bhi[rr][q+2] = h2; Bhi[rr][q+3] = h3;
            Blo[rr][q+0] = cvt_tf32(v.x - __uint_as_float(h0));
            Blo[rr][q+1] = cvt_tf32(v.y - __uint_as_float(h1));
            Blo[rr][q+2] = cvt_tf32(v.z - __uint_as_float(h2));
            Blo[rr][q+3] = cvt_tf32(v.w - __uint_as_float(h3));
        }
        __syncthreads();
#pragma unroll
        for (int k8 = 0; k8 < 2; k8++) {
            int kk = k8 * 8;
            unsigned ah[MT][4], al[MT][4], bh[NT][2], bl[NT][2];
#pragma unroll
            for (int mt = 0; mt < MT; mt++) {
                int rb = wm * (MT * 16) + mt * 16;
                ah[mt][0] = Ahi[rb + r][kk + t4];     al[mt][0] = Alo[rb + r][kk + t4];
                ah[mt][1] = Ahi[rb + r + 8][kk + t4]; al[mt][1] = Alo[rb + r + 8][kk + t4];
                ah[mt][2] = Ahi[rb + r][kk + t4 + 4]; al[mt][2] = Alo[rb + r][kk + t4 + 4];
                ah[mt][3] = Ahi[rb + r + 8][kk + t4 + 4]; al[mt][3] = Alo[rb + r + 8][kk + t4 + 4];
            }
#pragma unroll
            for (int nt = 0; nt < NT; nt++) {
                int cb = wn * (NT * 8) + nt * 8;
                bh[nt][0] = Bhi[cb + r][kk + t4];     bl[nt][0] = Blo[cb + r][kk + t4];
                bh[nt][1] = Bhi[cb + r][kk + t4 + 4]; bl[nt][1] = Blo[cb + r][kk + t4 + 4];
            }
#pragma unroll
            for (int mt = 0; mt < MT; mt++)
#pragma unroll
                for (int nt = 0; nt < NT; nt++) {
                    mma_tf32(acc[mt][nt], ah[mt], bh[nt]);
                    mma_tf32(acc[mt][nt], ah[mt], bl[nt]);
                    mma_tf32(acc[mt][nt], al[mt], bh[nt]);
                }
        }
    }

#pragma unroll
    for (int mt = 0; mt < MT; mt++) {
#pragma unroll
        for (int nt = 0; nt < NT; nt++) {
            int gm = m0 + wm * (MT * 16) + mt * 16 + r;
            int gn = n0 + wn * (NT * 8) + nt * 8 + t4 * 2;
            float b0 = bias[gn], b1 = bias[gn + 1];
            float v0 = acc[mt][nt][0] + b0, v1 = acc[mt][nt][1] + b1;
            float v2 = acc[mt][nt][2] + b0, v3 = acc[mt][nt][3] + b1;
            if (MODE == 0) {
                v0 = fmaxf(v0, 0.f); v1 = fmaxf(v1, 0.f);
                v2 = fmaxf(v2, 0.f); v3 = fmaxf(v3, 0.f);
            }
            *(float2*)&C[(size_t)gm * ldc + gn] = make_float2(v0, v1);
            *(float2*)&C[((size_t)gm + 8) * ldc + gn] = make_float2(v2, v3);
        }
    }
}

// ---------------- pooled path ----------------
__global__ __launch_bounds__(64) void k_zred(const float* __restrict__ z,
                                             const int* __restrict__ batch) {
    int c = threadIdx.x;
    int n0 = blockIdx.x * 128;
    int gp = batch[n0];
    float acc = 0.f, cnt = 0.f;
    for (int r = 0; r < 128; r++) {
        int n = n0 + r;
        int g = batch[n];
        float v = z[(size_t)n * LAT + c];
        if (g != gp) {
            atomicAdd(&g_zgsum[gp * LAT + c], acc);
            if (c == 0) atomicAdd(&g_cnt[gp], cnt);
            acc = 0.f; cnt = 0.f; gp = g;
        }
        acc += v; cnt += 1.f;
    }
    atomicAdd(&g_zgsum[gp * LAT + c], acc);
    if (c == 0) atomicAdd(&g_cnt[gp], cnt);
}

__global__ __launch_bounds__(128) void k_zg_gout(float* __restrict__ zg_out,
                                                 const float* __restrict__ dec_w,
                                                 const float* __restrict__ dec_b) {
    __shared__ float zg_s[LAT];
    int g = blockIdx.x, t = threadIdx.x;
    if (t < LAT) {
        float v = g_zgsum[g * LAT + t] / fmaxf(g_cnt[g], 1.0f);
        zg_s[t] = v;
        zg_out[g * LAT + t] = v;
    }
    __syncthreads();
    float s = dec_b[t];
#pragma unroll 8
    for (int k = 0; k < LAT; k++) s = fmaf(zg_s[k], dec_w[t * LAT + k], s);
    g_gout[g * IN_CH + t] = s;
}

__global__ void k_xhat(float* __restrict__ xh, const int* __restrict__ batch) {
    int t = blockIdx.x * blockDim.x + threadIdx.x;
    if (t < N_NODES * (IN_CH / 4)) {
        int n = t / (IN_CH / 4), q = t % (IN_CH / 4);
        int b = batch[n];
        float4 v = *(const float4*)&g_gout[b * IN_CH + q * 4];
        *(float4*)&xh[(size_t)n * IN_CH + q * 4] = v;
    }
}

// ---------------- a_hat = sigmoid(Z Z^T), symmetric upper-tri ----------------
#define NT_TILES (N_NODES / 128)
#define N_PAIRS  (NT_TILES * (NT_TILES + 1) / 2)
__global__ __launch_bounds__(256) void k_ahat(const float* __restrict__ z,
                                              float* __restrict__ out) {
    __shared__ union {
        struct { unsigned Zi[128][36]; unsigned Zj[128][36]; } ld;
        float tr[64][132];
    } sm;
    int tid = threadIdx.x;
    int warp = tid >> 5, lane = tid & 31;
    int wm = warp >> 2, wn = warp & 3;
    int r = lane >> 2, t4 = lane & 3;

    int L = blockIdx.x;
    int bj = (int)((sqrtf(8.0f * (float)L + 1.0f) - 1.0f) * 0.5f);
    while ((bj + 1) * (bj + 2) / 2 <= L) bj++;
    while (bj * (bj + 1) / 2 > L) bj--;
    int bi = L - bj * (bj + 1) / 2;
    int mb = bi << 7, nb = bj << 7;

    float acc[4][4][4];
#pragma unroll
    for (int mt = 0; mt < 4; mt++)
#pragma unroll
        for (int nt = 0; nt < 4; nt++)
#pragma unroll
            for (int q = 0; q < 4; q++) acc[mt][nt][q] = 0.0f;

#pragma unroll
    for (int kh = 0; kh < 2; kh++) {
        __syncthreads();
#pragma unroll
        for (int f = 0; f < 4; f++) {
            int id = f * 256 + tid;
            int row = id >> 3, q = id & 7;
            float4 vi = *(const float4*)&z[(size_t)(mb + row) * LAT + kh * 32 + q * 4];
            float4 vj = *(const float4*)&z[(size_t)(nb + row) * LAT + kh * 32 + q * 4];
            uint4 ui = make_uint4(cvt_tf32(vi.x), cvt_tf32(vi.y), cvt_tf32(vi.z), cvt_tf32(vi.w));
            uint4 uj = make_uint4(cvt_tf32(vj.x), cvt_tf32(vj.y), cvt_tf32(vj.z), cvt_tf32(vj.w));
            *(uint4*)&sm.ld.Zi[row][q * 4] = ui;
            *(uint4*)&sm.ld.Zj[row][q * 4] = uj;
        }
        __syncthreads();

#pragma unroll
        for (int k8 = 0; k8 < 4; k8++) {
            int kc = k8 * 8;
            unsigned a[4][4], b[4][2];
#pragma unroll
            for (int mt = 0; mt < 4; mt++) {
                int rb = wm * 64 + mt * 16;
                a[mt][0] = sm.ld.Zi[rb + r][kc + t4];
                a[mt][1] = sm.ld.Zi[rb + r + 8][kc + t4];
                a[mt][2] = sm.ld.Zi[rb + r][kc + t4 + 4];
                a[mt][3] = sm.ld.Zi[rb + r + 8][kc + t4 + 4];
            }
#pragma unroll
            for (int nt = 0; nt < 4; nt++) {
                int cb = wn * 32 + nt * 8;
                b[nt][0] = sm.ld.Zj[cb + r][kc + t4];
                b[nt][1] = sm.ld.Zj[cb + r][kc + t4 + 4];
            }
#pragma unroll
            for (int mt = 0; mt < 4; mt++)
#pragma unroll
                for (int nt = 0; nt < 4; nt++)
                    mma_tf32(acc[mt][nt], a[mt], b[nt]);
        }
    }

#pragma unroll
    for (int mt = 0; mt < 4; mt++)
#pragma unroll
        for (int nt = 0; nt < 4; nt++)
#pragma unroll
            for (int q = 0; q < 4; q++) acc[mt][nt][q] = sigf(acc[mt][nt][q]);

    // direct store of tile (mb, nb): stage via smem, float4 coalesced, 2 row-chunks
#pragma unroll
    for (int p = 0; p < 2; p++) {
        __syncthreads();
        if (wm == p) {
#pragma unroll
            for (int mt = 0; mt < 4; mt++) {
#pragma unroll
                for (int nt = 0; nt < 4; nt++) {
                    int rl = mt * 16 + r;               // 0..63 within chunk
                    int col = wn * 32 + nt * 8 + t4 * 2;
                    sm.tr[rl][col]         = acc[mt][nt][0];
                    sm.tr[rl][col + 1]     = acc[mt][nt][1];
                    sm.tr[rl + 8][col]     = acc[mt][nt][2];
                    sm.tr[rl + 8][col + 1] = acc[mt][nt][3];
                }
            }
        }
        __syncthreads();
        int rr = tid >> 2;
#pragma unroll
        for (int j = 0; j < 8; j++) {
            int col = (tid & 3) * 4 + j * 16;
            float4 v = *(float4*)&sm.tr[rr][col];
            __stcs((float4*)&out[(size_t)(mb + p * 64 + rr) * N_NODES + nb + col], v);
        }
    }

    if (bi == bj) return;

    // mirror store of tile (nb, mb): transpose via smem, 2 col-chunks
#pragma unroll
    for (int p = 0; p < 2; p++) {
        __syncthreads();
        if ((wn >> 1) == p) {
            int cbase = wn * 32 - p * 64;
#pragma unroll
            for (int mt = 0; mt < 4; mt++) {
#pragma unroll
                for (int nt = 0; nt < 4; nt++) {
                    int cc = cbase + nt * 8 + t4 * 2;
                    int rm0 = wm * 64 + mt * 16 + r;
                    sm.tr[cc + 0][rm0]     = acc[mt][nt][0];
                    sm.tr[cc + 1][rm0]     = acc[mt][nt][1];
                    sm.tr[cc + 0][rm0 + 8] = acc[mt][nt][2];
                    sm.tr[cc + 1][rm0 + 8] = acc[mt][nt][3];
                }
            }
        }
        __syncthreads();
        int cc = tid >> 2;
#pragma unroll
        for (int j = 0; j < 8; j++) {
            int col = (tid & 3) * 4 + j * 16;
            float4 v = *(float4*)&sm.tr[cc][col];
            __stcs((float4*)&out[(size_t)(nb + p * 64 + cc) * N_NODES + mb + col], v);
        }
    }
}

// ---------------- launcher ----------------
extern "C" void kernel_launch(void* const* d_in, const int* in_sizes, int n_in,
                              void* d_out_v, int out_size) {
    (void)in_sizes; (void)n_in; (void)out_size;
    const float* x     = (const float*)d_in[0];
    const int* ei      = (const int*)d_in[1];
    const int* bat     = (const int*)d_in[2];
    const float* gcn_w = (const float*)d_in[3];
    const float* gcn_b = (const float*)d_in[4];
    const float* lin_w = (const float*)d_in[5];
    const float* lin_b = (const float*)d_in[6];
    const float* dec_w = (const float*)d_in[7];
    const float* dec_b = (const float*)d_in[8];
    float* out = (float*)d_out_v;

    float *p_aggx, *p_h2;
    cudaGetSymbolAddress((void**)&p_aggx, g_aggx);
    cudaGetSymbolAddress((void**)&p_h2, g_h2);

    k_zero<<<(N_NODES + 255) / 256, 256>>>();                        // 0
    k_build<<<(N_EDGES + 255) / 256, 256>>>(ei);                     // 1
    k_gatherx<<<N_NODES / 4, 128>>>(x);                              // 2
    // h2 = relu(aggx @ gcn_w^T + b)
    gemm_mma<128, 128, IN_CH, 0><<<dim3(HID_CH / 128, N_NODES / 128), 256>>>(
        p_aggx, gcn_w, gcn_b, p_h2, HID_CH);                         // 3 (profiled)
    // z = h2 @ lin_w^T + lin_b   (M-tile 64 -> 256 blocks)
    gemm_mma<64, 64, HID_CH, 1><<<dim3(1, N_NODES / 64), 256>>>(
        p_h2, lin_w, lin_b, out + Z_OFF, LAT);                       // 4
    // a_hat
    k_ahat<<<N_PAIRS, 256>>>(out + Z_OFF, out + AH_OFF);             // 5
    // pooled path
    k_zred<<<N_NODES / 128, 64>>>(out + Z_OFF, bat);                 // 6
    k_zg_gout<<<N_GRAPHS, 128>>>(out + ZG_OFF, dec_w, dec_b);        // 7
    k_xhat<<<(N_NODES * (IN_CH / 4) + 255) / 256, 256>>>(out + XH_OFF, bat); // 8
}

// round 7
// speedup vs baseline: 1.2500x; 1.2500x over previous
#include <cuda_runtime.h>
#include <cuda_bf16.h>
#include <cstdint>

#define N_NODES 16384
#define N_EDGES 262144
#define N_GRAPHS 16
#define IN_CH 128
#define HID_CH 256
#define LAT 64
#define MAXDEG 96

#define Z_OFF   0
#define ZG_OFF  (N_NODES*LAT)
#define XH_OFF  (ZG_OFF + N_GRAPHS*LAT)
#define AH_OFF  (XH_OFF + N_NODES*IN_CH)

// ---------------- device scratch ----------------
__device__ float g_aggx[N_NODES*IN_CH];
__device__ float g_h2[N_NODES*HID_CH];
__device__ int   g_cnt_i[N_NODES];
__device__ int   g_csr[N_NODES*MAXDEG];
__device__ float g_zgsum[N_GRAPHS*LAT];
__device__ float g_cnt[N_GRAPHS];
__device__ float g_gout[N_GRAPHS*IN_CH];

// ---------------- helpers ----------------
__device__ __forceinline__ unsigned cvt_tf32(float x) {
    unsigned u;
    asm("cvt.rna.tf32.f32 %0, %1;" : "=r"(u) : "f"(x));
    return u;
}
__device__ __forceinline__ float sigf(float x) {
    float t;
    asm("tanh.approx.f32 %0, %1;" : "=f"(t) : "f"(x * 0.5f));
    return fmaf(0.5f, t, 0.5f);
}
__device__ __forceinline__ void mma_tf32(float* c, const unsigned* a, const unsigned* b) {
    asm volatile(
        "mma.sync.aligned.m16n8k8.row.col.f32.tf32.tf32.f32 "
        "{%0,%1,%2,%3},{%4,%5,%6,%7},{%8,%9},{%0,%1,%2,%3};\n"
        : "+f"(c[0]), "+f"(c[1]), "+f"(c[2]), "+f"(c[3])
        : "r"(a[0]), "r"(a[1]), "r"(a[2]), "r"(a[3]), "r"(b[0]), "r"(b[1]));
}

// ---------------- prep ----------------
__global__ void k_zero() {
    int i = blockIdx.x * blockDim.x + threadIdx.x;
    if (i < N_NODES) g_cnt_i[i] = 0;
    if (i < N_GRAPHS * LAT) g_zgsum[i] = 0.0f;
    if (i < N_GRAPHS) g_cnt[i] = 0.0f;
}

__global__ void k_build(const int* __restrict__ ei) {
    int e = blockIdx.x * blockDim.x + threadIdx.x;
    if (e < N_EDGES) {
        int row = ei[e];
        int col = ei[N_EDGES + e];
        int pos = atomicAdd(&g_cnt_i[col], 1);
        if (pos < MAXDEG) g_csr[col * MAXDEG + pos] = row;
    }
}

// agg_x[n] = dinv_n^2 * x[n] + sum_e dinv_n*dinv_src * x[src]   (128 ch)
__global__ __launch_bounds__(128) void k_gatherx(const float* __restrict__ x) {
    __shared__ float w_s[MAXDEG];
    __shared__ int   s_s[MAXDEG];
    int n = blockIdx.x, c = threadIdx.x;
    int dg = min(g_cnt_i[n], MAXDEG);
    float di = rsqrtf((float)(dg + 1));
    const int* lst = &g_csr[n * MAXDEG];
    if (c < dg) {
        int src = lst[c];
        s_s[c] = src;
        w_s[c] = di * rsqrtf((float)(g_cnt_i[src] + 1));
    }
    __syncthreads();
    float acc = di * di * x[(size_t)n * IN_CH + c];
#pragma unroll 4
    for (int e = 0; e < dg; e++)
        acc = fmaf(w_s[e], x[(size_t)s_s[e] * IN_CH + c], acc);
    g_aggx[(size_t)n * IN_CH + c] = acc;
}

// ---------------- split-tf32 MMA GEMM (R5 config: M-tile 128) ----------------
template<int NTILE, int KDIM, int MODE>   // MODE 0: bias+relu, 1: bias
__global__ __launch_bounds__(256) void gemm_mma(
    const float* __restrict__ A, const float* __restrict__ B,
    const float* __restrict__ bias, float* __restrict__ C, int ldc)
{
    constexpr int NT = NTILE / 32;
    __shared__ unsigned Ahi[128][20], Alo[128][20];
    __shared__ unsigned Bhi[NTILE][20], Blo[NTILE][20];
    int tid = threadIdx.x;
    int warp = tid >> 5, lane = tid & 31;
    int wm = warp >> 2, wn = warp & 3;
    int r = lane >> 2, t4 = lane & 3;
    int m0 = blockIdx.y * 128, n0 = blockIdx.x * NTILE;

    float acc[4][NT][4];
#pragma unroll
    for (int mt = 0; mt < 4; mt++)
#pragma unroll
        for (int nt = 0; nt < NT; nt++)
#pragma unroll
            for (int q = 0; q < 4; q++) acc[mt][nt][q] = 0.0f;

    for (int kc = 0; kc < KDIM; kc += 16) {
        __syncthreads();
        {
            int row = tid >> 2, q = (tid & 3) * 4;
#pragma unroll
            for (int h = 0; h < 2; h++) {
                int rr = row + h * 64;
                float4 v = *(const float4*)&A[(size_t)(m0 + rr) * KDIM + kc + q];
                unsigned h0 = cvt_tf32(v.x), h1 = cvt_tf32(v.y),
                         h2 = cvt_tf32(v.z), h3 = cvt_tf32(v.w);
                Ahi[rr][q+0] = h0; Ahi[rr][q+1] = h1; Ahi[rr][q+2] = h2; Ahi[rr][q+3] = h3;
                Alo[rr][q+0] = cvt_tf32(v.x - __uint_as_float(h0));
                Alo[rr][q+1] = cvt_tf32(v.y - __uint_as_float(h1));
                Alo[rr][q+2] = cvt_tf32(v.z - __uint_as_float(h2));
                Alo[rr][q+3] = cvt_tf32(v.w - __uint_as_float(h3));
            }
            for (int i = tid; i < NTILE * 4; i += 256) {
                int rr = i >> 2, q = (i & 3) * 4;
                float4 v = *(const float4*)&B[(size_t)(n0 + rr) * KDIM + kc + q];
                unsigned h0 = cvt_tf32(v.x), h1 = cvt_tf32(v.y),
                         h2 = cvt_tf32(v.z), h3 = cvt_tf32(v.w);
                Bhi[rr][q+0] = h0; Bhi[rr][q+1] = h1; Bhi[rr][q+2] = h2; Bhi[rr][q+3] = h3;
                Blo[rr][q+0] = cvt_tf32(v.x - __uint_as_float(h0));
                Blo[rr][q+1] = cvt_tf32(v.y - __uint_as_float(h1));
                Blo[rr][q+2] = cvt_tf32(v.z - __uint_as_float(h2));
                Blo[rr][q+3] = cvt_tf32(v.w - __uint_as_float(h3));
            }
        }
        __syncthreads();
#pragma unroll
        for (int k8 = 0; k8 < 2; k8++) {
            int kk = k8 * 8;
            unsigned ah[4][4], al[4][4], bh[NT][2], bl[NT][2];
#pragma unroll
            for (int mt = 0; mt < 4; mt++) {
                int rb = wm * 64 + mt * 16;
                ah[mt][0] = Ahi[rb + r][kk + t4];     al[mt][0] = Alo[rb + r][kk + t4];
                ah[mt][1] = Ahi[rb + r + 8][kk + t4]; al[mt][1] = Alo[rb + r + 8][kk + t4];
                ah[mt][2] = Ahi[rb + r][kk + t4 + 4]; al[mt][2] = Alo[rb + r][kk + t4 + 4];
                ah[mt][3] = Ahi[rb + r + 8][kk + t4 + 4]; al[mt][3] = Alo[rb + r + 8][kk + t4 + 4];
            }
#pragma unroll
            for (int nt = 0; nt < NT; nt++) {
                int cb = wn * (NT * 8) + nt * 8;
                bh[nt][0] = Bhi[cb + r][kk + t4];     bl[nt][0] = Blo[cb + r][kk + t4];
                bh[nt][1] = Bhi[cb + r][kk + t4 + 4]; bl[nt][1] = Blo[cb + r][kk + t4 + 4];
            }
#pragma unroll
            for (int mt = 0; mt < 4; mt++)
#pragma unroll
                for (int nt = 0; nt < NT; nt++) {
                    mma_tf32(acc[mt][nt], ah[mt], bh[nt]);
                    mma_tf32(acc[mt][nt], ah[mt], bl[nt]);
                    mma_tf32(acc[mt][nt], al[mt], bh[nt]);
                }
        }
    }

#pragma unroll
    for (int mt = 0; mt < 4; mt++) {
#pragma unroll
        for (int nt = 0; nt < NT; nt++) {
            int gm = m0 + wm * 64 + mt * 16 + r;
            int gn = n0 + wn * (NT * 8) + nt * 8 + t4 * 2;
            float b0 = bias[gn], b1 = bias[gn + 1];
            float v0 = acc[mt][nt][0] + b0, v1 = acc[mt][nt][1] + b1;
            float v2 = acc[mt][nt][2] + b0, v3 = acc[mt][nt][3] + b1;
            if (MODE == 0) {
                v0 = fmaxf(v0, 0.f); v1 = fmaxf(v1, 0.f);
                v2 = fmaxf(v2, 0.f); v3 = fmaxf(v3, 0.f);
            }
            *(float2*)&C[(size_t)gm * ldc + gn] = make_float2(v0, v1);
            *(float2*)&C[((size_t)gm + 8) * ldc + gn] = make_float2(v2, v3);
        }
    }
}

// ---------------- pooled path ----------------
__global__ __launch_bounds__(64) void k_zred(const float* __restrict__ z,
                                             const int* __restrict__ batch) {
    int c = threadIdx.x;
    int n0 = blockIdx.x * 128;
    int gp = batch[n0];
    float acc = 0.f, cnt = 0.f;
    for (int r = 0; r < 128; r++) {
        int n = n0 + r;
        int g = batch[n];
        float v = z[(size_t)n * LAT + c];
        if (g != gp) {
            atomicAdd(&g_zgsum[gp * LAT + c], acc);
            if (c == 0) atomicAdd(&g_cnt[gp], cnt);
            acc = 0.f; cnt = 0.f; gp = g;
        }
        acc += v; cnt += 1.f;
    }
    atomicAdd(&g_zgsum[gp * LAT + c], acc);
    if (c == 0) atomicAdd(&g_cnt[gp], cnt);
}

__global__ __launch_bounds__(128) void k_zg_gout(float* __restrict__ zg_out,
                                                 const float* __restrict__ dec_w,
                                                 const float* __restrict__ dec_b) {
    __shared__ float zg_s[LAT];
    int g = blockIdx.x, t = threadIdx.x;
    if (t < LAT) {
        float v = g_zgsum[g * LAT + t] / fmaxf(g_cnt[g], 1.0f);
        zg_s[t] = v;
        zg_out[g * LAT + t] = v;
    }
    __syncthreads();
    float s = dec_b[t];
#pragma unroll 8
    for (int k = 0; k < LAT; k++) s = fmaf(zg_s[k], dec_w[t * LAT + k], s);
    g_gout[g * IN_CH + t] = s;
}

__global__ void k_xhat(float* __restrict__ xh, const int* __restrict__ batch) {
    int t = blockIdx.x * blockDim.x + threadIdx.x;
    if (t < N_NODES * (IN_CH / 4)) {
        int n = t / (IN_CH / 4), q = t % (IN_CH / 4);
        int b = batch[n];
        float4 v = *(const float4*)&g_gout[b * IN_CH + q * 4];
        *(float4*)&xh[(size_t)n * IN_CH + q * 4] = v;
    }
}

// ---------------- a_hat = sigmoid(Z Z^T), symmetric upper-tri ----------------
// All stores direct from registers — NO smem epilogue staging, NO post-STS barriers.
#define NT_TILES (N_NODES / 128)
#define N_PAIRS  (NT_TILES * (NT_TILES + 1) / 2)
__global__ __launch_bounds__(256) void k_ahat(const float* __restrict__ z,
                                              float* __restrict__ out) {
    __shared__ unsigned Zi[128][36];
    __shared__ unsigned Zj[128][36];
    int tid = threadIdx.x;
    int warp = tid >> 5, lane = tid & 31;
    int wm = warp >> 2, wn = warp & 3;
    int r = lane >> 2, t4 = lane & 3;

    int L = blockIdx.x;
    int bj = (int)((sqrtf(8.0f * (float)L + 1.0f) - 1.0f) * 0.5f);
    while ((bj + 1) * (bj + 2) / 2 <= L) bj++;
    while (bj * (bj + 1) / 2 > L) bj--;
    int bi = L - bj * (bj + 1) / 2;
    int mb = bi << 7, nb = bj << 7;

    float acc[4][4][4];
#pragma unroll
    for (int mt = 0; mt < 4; mt++)
#pragma unroll
        for (int nt = 0; nt < 4; nt++)
#pragma unroll
            for (int q = 0; q < 4; q++) acc[mt][nt][q] = 0.0f;

#pragma unroll
    for (int kh = 0; kh < 2; kh++) {
        __syncthreads();
#pragma unroll
        for (int f = 0; f < 4; f++) {
            int id = f * 256 + tid;
            int row = id >> 3, q = id & 7;
            float4 vi = *(const float4*)&z[(size_t)(mb + row) * LAT + kh * 32 + q * 4];
            float4 vj = *(const float4*)&z[(size_t)(nb + row) * LAT + kh * 32 + q * 4];
            uint4 ui = make_uint4(cvt_tf32(vi.x), cvt_tf32(vi.y), cvt_tf32(vi.z), cvt_tf32(vi.w));
            uint4 uj = make_uint4(cvt_tf32(vj.x), cvt_tf32(vj.y), cvt_tf32(vj.z), cvt_tf32(vj.w));
            *(uint4*)&Zi[row][q * 4] = ui;
            *(uint4*)&Zj[row][q * 4] = uj;
        }
        __syncthreads();

#pragma unroll
        for (int k8 = 0; k8 < 4; k8++) {
            int kc = k8 * 8;
            unsigned a[4][4], b[4][2];
#pragma unroll
            for (int mt = 0; mt < 4; mt++) {
                int rb = wm * 64 + mt * 16;
                a[mt][0] = Zi[rb + r][kc + t4];
                a[mt][1] = Zi[rb + r + 8][kc + t4];
                a[mt][2] = Zi[rb + r][kc + t4 + 4];
                a[mt][3] = Zi[rb + r + 8][kc + t4 + 4];
            }
#pragma unroll
            for (int nt = 0; nt < 4; nt++) {
                int cb = wn * 32 + nt * 8;
                b[nt][0] = Zj[cb + r][kc + t4];
                b[nt][1] = Zj[cb + r][kc + t4 + 4];
            }
#pragma unroll
            for (int mt = 0; mt < 4; mt++)
#pragma unroll
                for (int nt = 0; nt < 4; nt++)
                    mma_tf32(acc[mt][nt], a[mt], b[nt]);
        }
    }

#pragma unroll
    for (int mt = 0; mt < 4; mt++)
#pragma unroll
        for (int nt = 0; nt < 4; nt++)
#pragma unroll
            for (int q = 0; q < 4; q++) acc[mt][nt][q] = sigf(acc[mt][nt][q]);

    // direct tile (mb, nb): register float2 stores (8 packed 32B sectors per instr)
#pragma unroll
    for (int mt = 0; mt < 4; mt++) {
#pragma unroll
        for (int nt = 0; nt < 4; nt++) {
            int gm = mb + wm * 64 + mt * 16 + r;
            int gn = nb + wn * 32 + nt * 8 + t4 * 2;
            __stcs((float2*)&out[(size_t)gm * N_NODES + gn],
                   make_float2(acc[mt][nt][0], acc[mt][nt][1]));
            __stcs((float2*)&out[((size_t)gm + 8) * N_NODES + gn],
                   make_float2(acc[mt][nt][2], acc[mt][nt][3]));
        }
    }

    if (bi == bj) return;

    // mirror tile (nb, mb): transposed register scalar stores.
    // Lanes sharing t4 (r=0..7) hit 8 consecutive gm in row gn -> packed 32B sectors.
#pragma unroll
    for (int mt = 0; mt < 4; mt++) {
#pragma unroll
        for (int nt = 0; nt < 4; nt++) {
            int gm = mb + wm * 64 + mt * 16 + r;
            int gn = nb + wn * 32 + nt * 8 + t4 * 2;
            __stcs(&out[(size_t)gn * N_NODES + gm],       acc[mt][nt][0]);
            __stcs(&out[((size_t)gn + 1) * N_NODES + gm], acc[mt][nt][1]);
            __stcs(&out[(size_t)gn * N_NODES + gm + 8],       acc[mt][nt][2]);
            __stcs(&out[((size_t)gn + 1) * N_NODES + gm + 8], acc[mt][nt][3]);
        }
    }
}

// ---------------- launcher ----------------
extern "C" void kernel_launch(void* const* d_in, const int* in_sizes, int n_in,
                              void* d_out_v, int out_size) {
    (void)in_sizes; (void)n_in; (void)out_size;
    const float* x     = (const float*)d_in[0];
    const int* ei      = (const int*)d_in[1];
    const int* bat     = (const int*)d_in[2];
    const float* gcn_w = (const float*)d_in[3];
    const float* gcn_b = (const float*)d_in[4];
    const float* lin_w = (const float*)d_in[5];
    const float* lin_b = (const float*)d_in[6];
    const float* dec_w = (const float*)d_in[7];
    const float* dec_b = (const float*)d_in[8];
    float* out = (float*)d_out_v;

    float *p_aggx, *p_h2;
    cudaGetSymbolAddress((void**)&p_aggx, g_aggx);
    cudaGetSymbolAddress((void**)&p_h2, g_h2);

    k_zero<<<(N_NODES + 255) / 256, 256>>>();                        // 0
    k_build<<<(N_EDGES + 255) / 256, 256>>>(ei);                     // 1
    k_gatherx<<<N_NODES, 128>>>(x);                                  // 2
    // h2 = relu(aggx @ gcn_w^T + b)
    gemm_mma<128, IN_CH, 0><<<dim3(HID_CH / 128, N_NODES / 128), 256>>>(
        p_aggx, gcn_w, gcn_b, p_h2, HID_CH);                         // 3 (profiled)
    // z = h2 @ lin_w^T + lin_b
    gemm_mma<64, HID_CH, 1><<<dim3(1, N_NODES / 128), 256>>>(
        p_h2, lin_w, lin_b, out + Z_OFF, LAT);                       // 4
    // a_hat
    k_ahat<<<N_PAIRS, 256>>>(out + Z_OFF, out + AH_OFF);             // 5
    // pooled path
    k_zred<<<N_NODES / 128, 64>>>(out + Z_OFF, bat);                 // 6
    k_zg_gout<<<N_GRAPHS, 128>>>(out + ZG_OFF, dec_w, dec_b);        // 7
    k_xhat<<<(N_NODES * (IN_CH / 4) + 255) / 256, 256>>>(out + XH_OFF, bat); // 8
}

// round 10
// speedup vs baseline: 1.3066x; 1.0452x over previous
#include <cuda_runtime.h>
#include <cuda_bf16.h>
#include <cstdint>

#define N_NODES 16384
#define N_EDGES 262144
#define N_GRAPHS 16
#define IN_CH 128
#define HID_CH 256
#define LAT 64
#define MAXDEG 96

#define Z_OFF   0
#define ZG_OFF  (N_NODES*LAT)
#define XH_OFF  (ZG_OFF + N_GRAPHS*LAT)
#define AH_OFF  (XH_OFF + N_NODES*IN_CH)

// ---------------- device scratch ----------------
__device__ float g_aggx[N_NODES*IN_CH];
__device__ float g_h2[N_NODES*HID_CH];
__device__ int   g_cnt_i[N_NODES];      // zero-init at load; reset by k_xhat each call
__device__ int   g_csr[N_NODES*MAXDEG];
__device__ float g_zgsum[N_GRAPHS*LAT]; // reset by k_xhat
__device__ float g_cnt[N_GRAPHS];       // reset by k_xhat
__device__ float g_gout[N_GRAPHS*IN_CH];

// ---------------- helpers ----------------
__device__ __forceinline__ unsigned cvt_tf32(float x) {
    unsigned u;
    asm("cvt.rna.tf32.f32 %0, %1;" : "=r"(u) : "f"(x));
    return u;
}
__device__ __forceinline__ float sigf(float x) {
    float t;
    asm("tanh.approx.f32 %0, %1;" : "=f"(t) : "f"(x * 0.5f));
    return fmaf(0.5f, t, 0.5f);
}
__device__ __forceinline__ void mma_tf32(float* c, const unsigned* a, const unsigned* b) {
    asm volatile(
        "mma.sync.aligned.m16n8k8.row.col.f32.tf32.tf32.f32 "
        "{%0,%1,%2,%3},{%4,%5,%6,%7},{%8,%9},{%0,%1,%2,%3};\n"
        : "+f"(c[0]), "+f"(c[1]), "+f"(c[2]), "+f"(c[3])
        : "r"(a[0]), "r"(a[1]), "r"(a[2]), "r"(a[3]), "r"(b[0]), "r"(b[1]));
}

// ---------------- prep ----------------
__global__ void k_build(const int* __restrict__ ei) {
    int e = blockIdx.x * blockDim.x + threadIdx.x;
    if (e < N_EDGES) {
        int row = ei[e];
        int col = ei[N_EDGES + e];
        int pos = atomicAdd(&g_cnt_i[col], 1);
        if (pos < MAXDEG) g_csr[col * MAXDEG + pos] = row;
    }
}

// agg_x[n] = dinv_n^2 * x[n] + sum_e dinv_n*dinv_src * x[src]   (128 ch)
__global__ __launch_bounds__(128) void k_gatherx(const float* __restrict__ x) {
    __shared__ float w_s[MAXDEG];
    __shared__ int   s_s[MAXDEG];
    int n = blockIdx.x, c = threadIdx.x;
    int dg = min(g_cnt_i[n], MAXDEG);
    float di = rsqrtf((float)(dg + 1));
    const int* lst = &g_csr[n * MAXDEG];
    if (c < dg) {
        int src = lst[c];
        s_s[c] = src;
        w_s[c] = di * rsqrtf((float)(g_cnt_i[src] + 1));
    }
    __syncthreads();
    float acc = di * di * x[(size_t)n * IN_CH + c];
#pragma unroll 4
    for (int e = 0; e < dg; e++)
        acc = fmaf(w_s[e], x[(size_t)s_s[e] * IN_CH + c], acc);
    g_aggx[(size_t)n * IN_CH + c] = acc;
}

// ---------------- single-tf32 MMA GEMM (M-tile 128, 8 warps 2x4) ----------------
template<int NTILE, int KDIM, int MODE>   // MODE 0: bias+relu, 1: bias
__global__ __launch_bounds__(256) void gemm_mma(
    const float* __restrict__ A, const float* __restrict__ B,
    const float* __restrict__ bias, float* __restrict__ C, int ldc)
{
    constexpr int NT = NTILE / 32;
    __shared__ unsigned Ahi[128][20];
    __shared__ unsigned Bhi[NTILE][20];
    int tid = threadIdx.x;
    int warp = tid >> 5, lane = tid & 31;
    int wm = warp >> 2, wn = warp & 3;
    int r = lane >> 2, t4 = lane & 3;
    int m0 = blockIdx.y * 128, n0 = blockIdx.x * NTILE;

    float acc[4][NT][4];
#pragma unroll
    for (int mt = 0; mt < 4; mt++)
#pragma unroll
        for (int nt = 0; nt < NT; nt++)
#pragma unroll
            for (int q = 0; q < 4; q++) acc[mt][nt][q] = 0.0f;

    for (int kc = 0; kc < KDIM; kc += 16) {
        __syncthreads();
        {
            int row = tid >> 2, q = (tid & 3) * 4;
#pragma unroll
            for (int h = 0; h < 2; h++) {
                int rr = row + h * 64;
                float4 v = *(const float4*)&A[(size_t)(m0 + rr) * KDIM + kc + q];
                Ahi[rr][q+0] = cvt_tf32(v.x); Ahi[rr][q+1] = cvt_tf32(v.y);
                Ahi[rr][q+2] = cvt_tf32(v.z); Ahi[rr][q+3] = cvt_tf32(v.w);
            }
            for (int i = tid; i < NTILE * 4; i += 256) {
                int rr = i >> 2, qq = (i & 3) * 4;
                float4 v = *(const float4*)&B[(size_t)(n0 + rr) * KDIM + kc + qq];
                Bhi[rr][qq+0] = cvt_tf32(v.x); Bhi[rr][qq+1] = cvt_tf32(v.y);
                Bhi[rr][qq+2] = cvt_tf32(v.z); Bhi[rr][qq+3] = cvt_tf32(v.w);
            }
        }
        __syncthreads();
#pragma unroll
        for (int k8 = 0; k8 < 2; k8++) {
            int kk = k8 * 8;
            unsigned ah[4][4], bh[NT][2];
#pragma unroll
            for (int mt = 0; mt < 4; mt++) {
                int rb = wm * 64 + mt * 16;
                ah[mt][0] = Ahi[rb + r][kk + t4];
                ah[mt][1] = Ahi[rb + r + 8][kk + t4];
                ah[mt][2] = Ahi[rb + r][kk + t4 + 4];
                ah[mt][3] = Ahi[rb + r + 8][kk + t4 + 4];
            }
#pragma unroll
            for (int nt = 0; nt < NT; nt++) {
                int cb = wn * (NT * 8) + nt * 8;
                bh[nt][0] = Bhi[cb + r][kk + t4];
                bh[nt][1] = Bhi[cb + r][kk + t4 + 4];
            }
#pragma unroll
            for (int mt = 0; mt < 4; mt++)
#pragma unroll
                for (int nt = 0; nt < NT; nt++)
                    mma_tf32(acc[mt][nt], ah[mt], bh[nt]);
        }
    }

#pragma unroll
    for (int mt = 0; mt < 4; mt++) {
#pragma unroll
        for (int nt = 0; nt < NT; nt++) {
            int gm = m0 + wm * 64 + mt * 16 + r;
            int gn = n0 + wn * (NT * 8) + nt * 8 + t4 * 2;
            float b0 = bias[gn], b1 = bias[gn + 1];
            float v0 = acc[mt][nt][0] + b0, v1 = acc[mt][nt][1] + b1;
            float v2 = acc[mt][nt][2] + b0, v3 = acc[mt][nt][3] + b1;
            if (MODE == 0) {
                v0 = fmaxf(v0, 0.f); v1 = fmaxf(v1, 0.f);
                v2 = fmaxf(v2, 0.f); v3 = fmaxf(v3, 0.f);
            }
            *(float2*)&C[(size_t)gm * ldc + gn] = make_float2(v0, v1);
            *(float2*)&C[((size_t)gm + 8) * ldc + gn] = make_float2(v2, v3);
        }
    }
}

// ---------------- pooled path ----------------
__global__ __launch_bounds__(64) void k_zred(const float* __restrict__ z,
                                             const int* __restrict__ batch) {
    int c = threadIdx.x;
    int n0 = blockIdx.x * 128;
    int gp = batch[n0];
    float acc = 0.f, cnt = 0.f;
    for (int r = 0; r < 128; r++) {
        int n = n0 + r;
        int g = batch[n];
        float v = z[(size_t)n * LAT + c];
        if (g != gp) {
            atomicAdd(&g_zgsum[gp * LAT + c], acc);
            if (c == 0) atomicAdd(&g_cnt[gp], cnt);
            acc = 0.f; cnt = 0.f; gp = g;
        }
        acc += v; cnt += 1.f;
    }
    atomicAdd(&g_zgsum[gp * LAT + c], acc);
    if (c == 0) atomicAdd(&g_cnt[gp], cnt);
}

__global__ __launch_bounds__(128) void k_zg_gout(float* __restrict__ zg_out,
                                                 const float* __restrict__ dec_w,
                                                 const float* __restrict__ dec_b) {
    __shared__ float zg_s[LAT];
    int g = blockIdx.x, t = threadIdx.x;
    if (t < LAT) {
        float v = g_zgsum[g * LAT + t] / fmaxf(g_cnt[g], 1.0f);
        zg_s[t] = v;
        zg_out[g * LAT + t] = v;
    }
    __syncthreads();
    float s = dec_b[t];
#pragma unroll 8
    for (int k = 0; k < LAT; k++) s = fmaf(zg_s[k], dec_w[t * LAT + k], s);
    g_gout[g * IN_CH + t] = s;
}

// x_hat broadcast + reset all per-call counters for the next graph replay
__global__ void k_xhat(float* __restrict__ xh, const int* __restrict__ batch) {
    int t = blockIdx.x * blockDim.x + threadIdx.x;
    if (t < N_NODES * (IN_CH / 4)) {
        int n = t / (IN_CH / 4), q = t % (IN_CH / 4);
        int b = batch[n];
        float4 v = *(const float4*)&g_gout[b * IN_CH + q * 4];
        *(float4*)&xh[(size_t)n * IN_CH + q * 4] = v;
    }
    if (t < N_NODES) g_cnt_i[t] = 0;
    if (t < N_GRAPHS * LAT) g_zgsum[t] = 0.0f;
    if (t < N_GRAPHS) g_cnt[t] = 0.0f;
}

// ---------------- a_hat = sigmoid(Z Z^T), symmetric upper-tri ----------------
// All stores direct from registers — NO smem epilogue staging (R7 proven config).
#define NT_TILES (N_NODES / 128)
#define N_PAIRS  (NT_TILES * (NT_TILES + 1) / 2)
__global__ __launch_bounds__(256) void k_ahat(const float* __restrict__ z,
                                              float* __restrict__ out) {
    __shared__ unsigned Zi[128][36];
    __shared__ unsigned Zj[128][36];
    int tid = threadIdx.x;
    int warp = tid >> 5, lane = tid & 31;
    int wm = warp >> 2, wn = warp & 3;
    int r = lane >> 2, t4 = lane & 3;

    int L = blockIdx.x;
    int bj = (int)((sqrtf(8.0f * (float)L + 1.0f) - 1.0f) * 0.5f);
    while ((bj + 1) * (bj + 2) / 2 <= L) bj++;
    while (bj * (bj + 1) / 2 > L) bj--;
    int bi = L - bj * (bj + 1) / 2;
    int mb = bi << 7, nb = bj << 7;

    float acc[4][4][4];
#pragma unroll
    for (int mt = 0; mt < 4; mt++)
#pragma unroll
        for (int nt = 0; nt < 4; nt++)
#pragma unroll
            for (int q = 0; q < 4; q++) acc[mt][nt][q] = 0.0f;

#pragma unroll
    for (int kh = 0; kh < 2; kh++) {
        __syncthreads();
#pragma unroll
        for (int f = 0; f < 4; f++) {
            int id = f * 256 + tid;
            int row = id >> 3, q = id & 7;
            float4 vi = *(const float4*)&z[(size_t)(mb + row) * LAT + kh * 32 + q * 4];
            float4 vj = *(const float4*)&z[(size_t)(nb + row) * LAT + kh * 32 + q * 4];
            uint4 ui = make_uint4(cvt_tf32(vi.x), cvt_tf32(vi.y), cvt_tf32(vi.z), cvt_tf32(vi.w));
            uint4 uj = make_uint4(cvt_tf32(vj.x), cvt_tf32(vj.y), cvt_tf32(vj.z), cvt_tf32(vj.w));
            *(uint4*)&Zi[row][q * 4] = ui;
            *(uint4*)&Zj[row][q * 4] = uj;
        }
        __syncthreads();

#pragma unroll
        for (int k8 = 0; k8 < 4; k8++) {
            int kc = k8 * 8;
            unsigned a[4][4], b[4][2];
#pragma unroll
            for (int mt = 0; mt < 4; mt++) {
                int rb = wm * 64 + mt * 16;
                a[mt][0] = Zi[rb + r][kc + t4];
                a[mt][1] = Zi[rb + r + 8][kc + t4];
                a[mt][2] = Zi[rb + r][kc + t4 + 4];
                a[mt][3] = Zi[rb + r + 8][kc + t4 + 4];
            }
#pragma unroll
            for (int nt = 0; nt < 4; nt++) {
                int cb = wn * 32 + nt * 8;
                b[nt][0] = Zj[cb + r][kc + t4];
                b[nt][1] = Zj[cb + r][kc + t4 + 4];
            }
#pragma unroll
            for (int mt = 0; mt < 4; mt++)
#pragma unroll
                for (int nt = 0; nt < 4; nt++)
                    mma_tf32(acc[mt][nt], a[mt], b[nt]);
        }
    }

#pragma unroll
    for (int mt = 0; mt < 4; mt++)
#pragma unroll
        for (int nt = 0; nt < 4; nt++)
#pragma unroll
            for (int q = 0; q < 4; q++) acc[mt][nt][q] = sigf(acc[mt][nt][q]);

    // direct tile (mb, nb): register float2 stores
#pragma unroll
    for (int mt = 0; mt < 4; mt++) {
#pragma unroll
        for (int nt = 0; nt < 4; nt++) {
            int gm = mb + wm * 64 + mt * 16 + r;
            int gn = nb + wn * 32 + nt * 8 + t4 * 2;
            __stcs((float2*)&out[(size_t)gm * N_NODES + gn],
                   make_float2(acc[mt][nt][0], acc[mt][nt][1]));
            __stcs((float2*)&out[((size_t)gm + 8) * N_NODES + gn],
                   make_float2(acc[mt][nt][2], acc[mt][nt][3]));
        }
    }

    if (bi == bj) return;

    // mirror tile (nb, mb): transposed register scalar stores (sector-packed)
#pragma unroll
    for (int mt = 0; mt < 4; mt++) {
#pragma unroll
        for (int nt = 0; nt < 4; nt++) {
            int gm = mb + wm * 64 + mt * 16 + r;
            int gn = nb + wn * 32 + nt * 8 + t4 * 2;
            __stcs(&out[(size_t)gn * N_NODES + gm],       acc[mt][nt][0]);
            __stcs(&out[((size_t)gn + 1) * N_NODES + gm], acc[mt][nt][1]);
            __stcs(&out[(size_t)gn * N_NODES + gm + 8],       acc[mt][nt][2]);
            __stcs(&out[((size_t)gn + 1) * N_NODES + gm + 8], acc[mt][nt][3]);
        }
    }
}

// ---------------- launcher ----------------
extern "C" void kernel_launch(void* const* d_in, const int* in_sizes, int n_in,
                              void* d_out_v, int out_size) {
    (void)in_sizes; (void)n_in; (void)out_size;
    const float* x     = (const float*)d_in[0];
    const int* ei      = (const int*)d_in[1];
    const int* bat     = (const int*)d_in[2];
    const float* gcn_w = (const float*)d_in[3];
    const float* gcn_b = (const float*)d_in[4];
    const float* lin_w = (const float*)d_in[5];
    const float* lin_b = (const float*)d_in[6];
    const float* dec_w = (const float*)d_in[7];
    const float* dec_b = (const float*)d_in[8];
    float* out = (float*)d_out_v;

    float *p_aggx, *p_h2;
    cudaGetSymbolAddress((void**)&p_aggx, g_aggx);
    cudaGetSymbolAddress((void**)&p_h2, g_h2);

    k_build<<<(N_EDGES + 255) / 256, 256>>>(ei);                     // 0
    k_gatherx<<<N_NODES, 128>>>(x);                                  // 1
    // h2 = relu(aggx @ gcn_w^T + b)
    gemm_mma<128, IN_CH, 0><<<dim3(HID_CH / 128, N_NODES / 128), 256>>>(
        p_aggx, gcn_w, gcn_b, p_h2, HID_CH);                         // 2
    // z = h2 @ lin_w^T + lin_b
    gemm_mma<64, HID_CH, 1><<<dim3(1, N_NODES / 128), 256>>>(
        p_h2, lin_w, lin_b, out + Z_OFF, LAT);                       // 3 (profiled)
    // a_hat
    k_ahat<<<N_PAIRS, 256>>>(out + Z_OFF, out + AH_OFF);             // 4
    // pooled path
    k_zred<<<N_NODES / 128, 64>>>(out + Z_OFF, bat);                 // 5
    k_zg_gout<<<N_GRAPHS, 128>>>(out + ZG_OFF, dec_w, dec_b);        // 6
    k_xhat<<<(N_NODES * (IN_CH / 4) + 255) / 256, 256>>>(out + XH_OFF, bat); // 7
}